// round 2
// baseline (speedup 1.0000x reference)
#include <cuda_runtime.h>

#define NN 100000
#define NE 1600000
#define IND 75
#define H 64
#define HB 16

// Scratch (allocation-free rule: __device__ globals)
__device__ __align__(256) float g_hA[NN * H];
__device__ __align__(256) float g_hB[NN * H];
__device__ __align__(256) float g_P[NN * H];
__device__ __align__(256) float g_agg[NN * H];

// ---------------------------------------------------------------------------
// proj: out = x @ W(75x64) + b     (run once)
// block 256 = 8 warps; warp handles 4 nodes, each thread 8 cols. Tile = 32 nodes.
// ---------------------------------------------------------------------------
__global__ __launch_bounds__(256) void proj_kernel(const float* __restrict__ x,
                                                   const float* __restrict__ w,
                                                   const float* __restrict__ b,
                                                   float* __restrict__ out) {
    __shared__ float sW[IND][H];       // 19200 B
    __shared__ float sA[32][IND + 1];  // 9728 B (pad 76 -> conflict-free)
    for (int i = threadIdx.x; i < IND * H; i += 256) sW[i / H][i % H] = w[i];

    const int lane = threadIdx.x & 31, wid = threadIdx.x >> 5;
    const int nl = lane & 3, cg = lane >> 2;
    const int myn = wid * 4 + nl;
    const float4 bb0 = *(const float4*)&b[cg * 8];
    const float4 bb1 = *(const float4*)&b[cg * 8 + 4];

    for (int tile = blockIdx.x; tile < NN / 32; tile += gridDim.x) {
        const int base = tile * 32;
        __syncthreads();
        for (int i = threadIdx.x; i < 32 * IND; i += 256)
            sA[i / IND][i % IND] = x[(size_t)base * IND + i];
        __syncthreads();

        float acc[8] = {bb0.x, bb0.y, bb0.z, bb0.w, bb1.x, bb1.y, bb1.z, bb1.w};
#pragma unroll 5
        for (int k = 0; k < IND; k++) {
            const float a = sA[myn][k];
            const float4 w0 = *(const float4*)&sW[k][cg * 8];
            const float4 w1 = *(const float4*)&sW[k][cg * 8 + 4];
            acc[0] += a * w0.x; acc[1] += a * w0.y; acc[2] += a * w0.z; acc[3] += a * w0.w;
            acc[4] += a * w1.x; acc[5] += a * w1.y; acc[6] += a * w1.z; acc[7] += a * w1.w;
        }
        const size_t o = (size_t)(base + myn) * H + cg * 8;
        *(float4*)&out[o]     = make_float4(acc[0], acc[1], acc[2], acc[3]);
        *(float4*)&out[o + 4] = make_float4(acc[4], acc[5], acc[6], acc[7]);
    }
}

// ---------------------------------------------------------------------------
// pk: P = h @ W2h(64x64) + b2, and zero agg (fused).
// ---------------------------------------------------------------------------
__global__ __launch_bounds__(256) void pk_kernel(const float* __restrict__ h,
                                                 const float* __restrict__ w,
                                                 const float* __restrict__ b,
                                                 float* __restrict__ P,
                                                 float* __restrict__ agg) {
    __shared__ float sW[H][H];       // 16384 B
    __shared__ float sA[32][H + 1];  // 8320 B (pad 65)
    for (int i = threadIdx.x; i < H * H; i += 256) sW[i >> 6][i & 63] = w[i];

    const int lane = threadIdx.x & 31, wid = threadIdx.x >> 5;
    const int nl = lane & 3, cg = lane >> 2;
    const int myn = wid * 4 + nl;
    const float4 bb0 = *(const float4*)&b[cg * 8];
    const float4 bb1 = *(const float4*)&b[cg * 8 + 4];
    const float4 z4 = make_float4(0.f, 0.f, 0.f, 0.f);

    for (int tile = blockIdx.x; tile < NN / 32; tile += gridDim.x) {
        const int base = tile * 32;
        __syncthreads();
        for (int i = threadIdx.x; i < 32 * H; i += 256)
            sA[i >> 6][i & 63] = h[(size_t)base * H + i];
        __syncthreads();

        float acc[8] = {bb0.x, bb0.y, bb0.z, bb0.w, bb1.x, bb1.y, bb1.z, bb1.w};
#pragma unroll 8
        for (int k = 0; k < H; k++) {
            const float a = sA[myn][k];
            const float4 w0 = *(const float4*)&sW[k][cg * 8];
            const float4 w1 = *(const float4*)&sW[k][cg * 8 + 4];
            acc[0] += a * w0.x; acc[1] += a * w0.y; acc[2] += a * w0.z; acc[3] += a * w0.w;
            acc[4] += a * w1.x; acc[5] += a * w1.y; acc[6] += a * w1.z; acc[7] += a * w1.w;
        }
        const size_t o = (size_t)(base + myn) * H + cg * 8;
        *(float4*)&P[o]     = make_float4(acc[0], acc[1], acc[2], acc[3]);
        *(float4*)&P[o + 4] = make_float4(acc[4], acc[5], acc[6], acc[7]);
        *(float4*)&agg[o]     = z4;
        *(float4*)&agg[o + 4] = z4;
    }
}

// ---------------------------------------------------------------------------
// edge: for each edge e: m = leakyrelu(P[src] + e_attr @ W2e); agg[dst] += m
// warp handles 2 consecutive edges: lanes 0-15 -> edge 2p, 16-31 -> edge 2p+1.
// Each lane owns 4 columns (float4), scatter via red.global.add.v4.f32.
// edge_index is delivered as int32 by the harness (int64 unsupported).
// ---------------------------------------------------------------------------
__global__ __launch_bounds__(256) void edge_kernel(const int* __restrict__ esrc,
                                                   const int* __restrict__ edst,
                                                   const float* __restrict__ eattr,
                                                   const float* __restrict__ w2e,
                                                   const float* __restrict__ P,
                                                   float* __restrict__ agg) {
    __shared__ float sW[HB][H];  // 4096 B
    for (int i = threadIdx.x; i < HB * H; i += 256) sW[i >> 6][i & 63] = w2e[i];
    __syncthreads();

    const int lane = threadIdx.x & 31;
    const int gw = blockIdx.x * 8 + (threadIdx.x >> 5);
    const int nw = gridDim.x * 8;
    const int half = lane >> 4, hl = lane & 15;

    for (int p = gw; p < NE / 2; p += nw) {
        const int e = 2 * p + half;
        const int src = esrc[e];
        const int dst = edst[e];
        if ((unsigned)src >= NN || (unsigned)dst >= NN) continue;  // dtype-guess guard
        const float ev = eattr[(size_t)e * HB + hl];

        float4 acc = *(const float4*)(P + (size_t)src * H + hl * 4);
#pragma unroll
        for (int k = 0; k < HB; k++) {
            const float ek = __shfl_sync(0xffffffffu, ev, k, 16);
            const float4 wv = *(const float4*)&sW[k][hl * 4];
            acc.x += ek * wv.x; acc.y += ek * wv.y;
            acc.z += ek * wv.z; acc.w += ek * wv.w;
        }
        // leaky_relu(x, 0.1) == max(x, 0.1x)
        acc.x = fmaxf(acc.x, 0.1f * acc.x);
        acc.y = fmaxf(acc.y, 0.1f * acc.y);
        acc.z = fmaxf(acc.z, 0.1f * acc.z);
        acc.w = fmaxf(acc.w, 0.1f * acc.w);

        float* dp = agg + (size_t)dst * H + hl * 4;
        asm volatile("red.global.add.v4.f32 [%0], {%1, %2, %3, %4};"
                     :: "l"(dp), "f"(acc.x), "f"(acc.y), "f"(acc.z), "f"(acc.w)
                     : "memory");
    }
}

// ---------------------------------------------------------------------------
// upd: out = concat(h, agg) @ W1(128x64) + b1
// smem: sW 32KB + sA 16KB (XOR swizzle instead of padding) = 48KB exactly.
// ---------------------------------------------------------------------------
__global__ __launch_bounds__(256) void upd_kernel(const float* __restrict__ h,
                                                  const float* __restrict__ agg,
                                                  const float* __restrict__ w,
                                                  const float* __restrict__ b,
                                                  float* __restrict__ out) {
    __shared__ float sW[2 * H][H];   // 32768 B
    __shared__ float sA[32][2 * H];  // 16384 B, XOR-swizzled by (row&3)<<3
    for (int i = threadIdx.x; i < 2 * H * H; i += 256) sW[i >> 6][i & 63] = w[i];

    const int lane = threadIdx.x & 31, wid = threadIdx.x >> 5;
    const int nl = lane & 3, cg = lane >> 2;
    const int myn = wid * 4 + nl;
    const int swz = nl << 3;
    const float4 bb0 = *(const float4*)&b[cg * 8];
    const float4 bb1 = *(const float4*)&b[cg * 8 + 4];

    for (int tile = blockIdx.x; tile < NN / 32; tile += gridDim.x) {
        const int base = tile * 32;
        __syncthreads();
        for (int i = threadIdx.x; i < 32 * H; i += 256) {
            const int r = i >> 6, c = i & 63;
            const int s = (r & 3) << 3;
            sA[r][c ^ s]        = h[(size_t)base * H + i];
            sA[r][(c + 64) ^ s] = agg[(size_t)base * H + i];
        }
        __syncthreads();

        float acc[8] = {bb0.x, bb0.y, bb0.z, bb0.w, bb1.x, bb1.y, bb1.z, bb1.w};
#pragma unroll 8
        for (int k = 0; k < 2 * H; k++) {
            const float a = sA[myn][k ^ swz];
            const float4 w0 = *(const float4*)&sW[k][cg * 8];
            const float4 w1 = *(const float4*)&sW[k][cg * 8 + 4];
            acc[0] += a * w0.x; acc[1] += a * w0.y; acc[2] += a * w0.z; acc[3] += a * w0.w;
            acc[4] += a * w1.x; acc[5] += a * w1.y; acc[6] += a * w1.z; acc[7] += a * w1.w;
        }
        const size_t o = (size_t)(base + myn) * H + cg * 8;
        *(float4*)&out[o]     = make_float4(acc[0], acc[1], acc[2], acc[3]);
        *(float4*)&out[o + 4] = make_float4(acc[4], acc[5], acc[6], acc[7]);
    }
}

// ---------------------------------------------------------------------------
extern "C" void kernel_launch(void* const* d_in, const int* in_sizes, int n_in,
                              void* d_out, int out_size) {
    const float* x      = (const float*)d_in[0];   // [100000, 75]
    const int*   eidx   = (const int*)d_in[1];     // [2, 1600000] (int64 -> int32 in harness)
    const float* eattr  = (const float*)d_in[2];   // [1600000, 16]
    const float* proj_w = (const float*)d_in[3];   // [75, 64]
    const float* proj_b = (const float*)d_in[4];   // [64]
    const float* u2w    = (const float*)d_in[5];   // [3, 80, 64]
    const float* u2b    = (const float*)d_in[6];   // [3, 64]
    const float* u1w    = (const float*)d_in[7];   // [3, 128, 64]
    const float* u1b    = (const float*)d_in[8];   // [3, 64]
    float*       out    = (float*)d_out;           // [100000, 64]

    float *hA, *hB, *P, *agg;
    cudaGetSymbolAddress((void**)&hA, g_hA);
    cudaGetSymbolAddress((void**)&hB, g_hB);
    cudaGetSymbolAddress((void**)&P, g_P);
    cudaGetSymbolAddress((void**)&agg, g_agg);

    proj_kernel<<<592, 256>>>(x, proj_w, proj_b, hA);

    for (int l = 0; l < 3; l++) {
        const float* hin = (l == 1) ? hB : hA;          // l0:A, l1:B, l2:A
        float* hout = (l == 0) ? hB : ((l == 1) ? hA : out);
        const float* w2 = u2w + (size_t)l * 80 * 64;     // rows 0..63 = W2h, 64..79 = W2e
        pk_kernel<<<592, 256>>>(hin, w2, u2b + l * 64, P, agg);
        edge_kernel<<<1184, 256>>>(eidx, eidx + NE, eattr, w2 + 64 * 64, P, agg);
        upd_kernel<<<592, 256>>>(hin, agg, u1w + (size_t)l * 128 * 64, u1b + l * 64, hout);
    }
}